// round 3
// baseline (speedup 1.0000x reference)
#include <cuda_runtime.h>

// ---------------------------------------------------------------------------
// ViT self-attention, fp32 baseline.
// B=16, N=1024, C=768, H=12, Dh=64. M_TOK = B*N = 16384.
//
// Reference quirk: q.reshape(B*H, N, Dh) WITHOUT transpose => each group g
// is the contiguous 1024x64 block at flat offset g*65536 of the (B,N,C)
// projection output. Output un-transpose: group g=b*12+h, row l, dim d
// -> ctx[b, l, h*64 + d]  (row stride 768).
// ---------------------------------------------------------------------------

#define M_TOK 16384
#define CDIM  768
#define SSTR  68   // shared-tile row stride (floats): 68*4=272 bytes, 16B-aligned

__device__ float g_q[M_TOK * CDIM];
__device__ float g_k[M_TOK * CDIM];
__device__ float g_v[M_TOK * CDIM];
__device__ float g_ctx[M_TOK * CDIM];

// ---------------------------------------------------------------------------
// 128x128x8 tiled SGEMM with bias epilogue: C[M,N] = A[M,K] @ B[K,N] + bias[N]
// 256 threads, 8x8 per thread. All dims divisible by tiles (16384, 768, 768).
// ---------------------------------------------------------------------------
__global__ __launch_bounds__(256) void sgemm_bias(
    const float* __restrict__ A, const float* __restrict__ B,
    const float* __restrict__ bias, float* __restrict__ C,
    int M, int N, int K)
{
    __shared__ float As[8][128];
    __shared__ float Bs[8][128];

    const int tid = threadIdx.x;
    const int tx = tid & 15;        // 0..15 -> N direction
    const int ty = tid >> 4;        // 0..15 -> M direction
    const int bx = blockIdx.x;      // N tile
    const int by = blockIdx.y;      // M tile

    const float* Ap = A + (size_t)(by * 128) * K;
    const float* Bp = B + bx * 128;

    const int aRow = tid >> 1;          // 0..127
    const int aCol = (tid & 1) * 4;     // 0 or 4
    const int bRow = tid >> 5;          // 0..7
    const int bCol = (tid & 31) * 4;    // 0..124

    float acc[8][8];
#pragma unroll
    for (int i = 0; i < 8; i++)
#pragma unroll
        for (int j = 0; j < 8; j++) acc[i][j] = 0.0f;

    for (int k0 = 0; k0 < K; k0 += 8) {
        float4 a = *(const float4*)(Ap + (size_t)aRow * K + k0 + aCol);
        As[aCol + 0][aRow] = a.x;
        As[aCol + 1][aRow] = a.y;
        As[aCol + 2][aRow] = a.z;
        As[aCol + 3][aRow] = a.w;
        *(float4*)&Bs[bRow][bCol] =
            *(const float4*)(Bp + (size_t)(k0 + bRow) * N + bCol);
        __syncthreads();

#pragma unroll
        for (int kk = 0; kk < 8; kk++) {
            float ar[8], br[8];
            *(float4*)(ar + 0) = *(float4*)&As[kk][ty * 8 + 0];
            *(float4*)(ar + 4) = *(float4*)&As[kk][ty * 8 + 4];
            *(float4*)(br + 0) = *(float4*)&Bs[kk][tx * 8 + 0];
            *(float4*)(br + 4) = *(float4*)&Bs[kk][tx * 8 + 4];
#pragma unroll
            for (int i = 0; i < 8; i++)
#pragma unroll
                for (int j = 0; j < 8; j++)
                    acc[i][j] = fmaf(ar[i], br[j], acc[i][j]);
        }
        __syncthreads();
    }

#pragma unroll
    for (int i = 0; i < 8; i++) {
        const int row = by * 128 + ty * 8 + i;
#pragma unroll
        for (int j = 0; j < 8; j += 4) {
            const int col = bx * 128 + tx * 8 + j;
            float4 o;
            o.x = acc[i][j + 0] + bias[col + 0];
            o.y = acc[i][j + 1] + bias[col + 1];
            o.z = acc[i][j + 2] + bias[col + 2];
            o.w = acc[i][j + 3] + bias[col + 3];
            *(float4*)(C + (size_t)row * N + col) = o;
        }
    }
}

// ---------------------------------------------------------------------------
// Flash attention over 192 contiguous (1024 x 64) groups.
// Grid: (16 q-tiles, 192 groups). Block: 256 threads (16x16), each thread
// owns a 4x4 tile of S/P and of O. Online softmax, fp32 throughout.
// Shared (dynamic): Qst[64][SSTR] (d-major), KP[64][SSTR] (K d-major, reused
// as P row-major stride SSTR), Vs[64][64] natural.
// ---------------------------------------------------------------------------
__global__ __launch_bounds__(256) void attn_kernel(
    const float* __restrict__ Q, const float* __restrict__ K,
    const float* __restrict__ V, float* __restrict__ ctx)
{
    extern __shared__ float sh[];
    float* Qst = sh;                        // 64*SSTR floats
    float* KP  = sh + 64 * SSTR;            // 64*SSTR floats
    float* Vs  = sh + 2 * 64 * SSTR;        // 64*64 floats

    const int g   = blockIdx.y;      // group 0..191
    const int qt  = blockIdx.x;      // q tile 0..15
    const int tid = threadIdx.x;
    const int tx  = tid & 15;        // key/dim direction
    const int ty  = tid >> 4;        // query direction
    const float scale = 0.125f;      // 1/sqrt(64)

    const float* Qg = Q + (size_t)g * 65536 + (size_t)qt * 4096;
    const float* Kg = K + (size_t)g * 65536;
    const float* Vg = V + (size_t)g * 65536;

    // Load Q tile transposed: Qst[d][i]  (4096 floats = 4 x 1024)
#pragma unroll
    for (int it = 0; it < 4; it++) {
        const int lin = it * 1024 + tid * 4;
        const int i = lin >> 6;
        const int d = lin & 63;
        float4 qv = *(const float4*)(Qg + lin);
        Qst[(d + 0) * SSTR + i] = qv.x;
        Qst[(d + 1) * SSTR + i] = qv.y;
        Qst[(d + 2) * SSTR + i] = qv.z;
        Qst[(d + 3) * SSTR + i] = qv.w;
    }

    float o[4][4];
    float m[4], l[4];
#pragma unroll
    for (int i = 0; i < 4; i++) {
        m[i] = -1e30f; l[i] = 0.0f;
#pragma unroll
        for (int j = 0; j < 4; j++) o[i][j] = 0.0f;
    }

    for (int kt = 0; kt < 16; kt++) {
        __syncthreads();   // previous iteration done reading KP (as P) / Vs
#pragma unroll
        for (int it = 0; it < 4; it++) {
            const int lin = it * 1024 + tid * 4;
            const int j = lin >> 6;
            const int d = lin & 63;
            float4 kv = *(const float4*)(Kg + kt * 4096 + lin);
            KP[(d + 0) * SSTR + j] = kv.x;
            KP[(d + 1) * SSTR + j] = kv.y;
            KP[(d + 2) * SSTR + j] = kv.z;
            KP[(d + 3) * SSTR + j] = kv.w;
            *(float4*)(Vs + lin) = *(const float4*)(Vg + kt * 4096 + lin);
        }
        __syncthreads();

        // S = Q K^T (4x4 per thread)
        float s[4][4];
#pragma unroll
        for (int i = 0; i < 4; i++)
#pragma unroll
            for (int j = 0; j < 4; j++) s[i][j] = 0.0f;

#pragma unroll 8
        for (int d = 0; d < 64; d++) {
            float4 qv = *(float4*)&Qst[d * SSTR + ty * 4];
            float4 kv = *(float4*)&KP [d * SSTR + tx * 4];
            float ar[4] = {qv.x, qv.y, qv.z, qv.w};
            float br[4] = {kv.x, kv.y, kv.z, kv.w};
#pragma unroll
            for (int i = 0; i < 4; i++)
#pragma unroll
                for (int j = 0; j < 4; j++)
                    s[i][j] = fmaf(ar[i], br[j], s[i][j]);
        }

        // online softmax stats (reduce over 16 lanes with same ty)
#pragma unroll
        for (int i = 0; i < 4; i++) {
#pragma unroll
            for (int j = 0; j < 4; j++) s[i][j] *= scale;
            float tm = fmaxf(fmaxf(s[i][0], s[i][1]), fmaxf(s[i][2], s[i][3]));
#pragma unroll
            for (int off = 8; off > 0; off >>= 1)
                tm = fmaxf(tm, __shfl_xor_sync(0xffffffffu, tm, off));
            const float nm = fmaxf(m[i], tm);
            const float f  = __expf(m[i] - nm);
            m[i] = nm;
            float rs = 0.0f;
#pragma unroll
            for (int j = 0; j < 4; j++) {
                s[i][j] = __expf(s[i][j] - nm);
                rs += s[i][j];
            }
#pragma unroll
            for (int off = 8; off > 0; off >>= 1)
                rs += __shfl_xor_sync(0xffffffffu, rs, off);
            l[i] = l[i] * f + rs;
#pragma unroll
            for (int j = 0; j < 4; j++) o[i][j] *= f;
        }

        __syncthreads();   // all threads done reading KP as K
        // write P into KP (row-major, stride SSTR)
#pragma unroll
        for (int i = 0; i < 4; i++) {
            float4 pv = make_float4(s[i][0], s[i][1], s[i][2], s[i][3]);
            *(float4*)&KP[(ty * 4 + i) * SSTR + tx * 4] = pv;
        }
        __syncthreads();

        // O += P @ V
#pragma unroll 8
        for (int jj = 0; jj < 64; jj++) {
            float4 vv = *(float4*)&Vs[jj * 64 + tx * 4];
            float pv[4];
#pragma unroll
            for (int i = 0; i < 4; i++) pv[i] = KP[(ty * 4 + i) * SSTR + jj];
#pragma unroll
            for (int i = 0; i < 4; i++) {
                o[i][0] = fmaf(pv[i], vv.x, o[i][0]);
                o[i][1] = fmaf(pv[i], vv.y, o[i][1]);
                o[i][2] = fmaf(pv[i], vv.z, o[i][2]);
                o[i][3] = fmaf(pv[i], vv.w, o[i][3]);
            }
        }
    }

    // Write O to ctx with the un-transpose: ctx[b, l, h*64 + d]
    const int b = g / 12;
    const int h = g % 12;
    float* outp = ctx + (size_t)b * 1024 * 768 + (size_t)(qt * 64) * 768 + h * 64;
#pragma unroll
    for (int i = 0; i < 4; i++) {
        const float inv = 1.0f / l[i];
        const int row = ty * 4 + i;
        float4 ov = make_float4(o[i][0] * inv, o[i][1] * inv,
                                o[i][2] * inv, o[i][3] * inv);
        *(float4*)(outp + (size_t)row * 768 + tx * 4) = ov;
    }
}

// ---------------------------------------------------------------------------
// Launch
// ---------------------------------------------------------------------------
extern "C" void kernel_launch(void* const* d_in, const int* in_sizes, int n_in,
                              void* d_out, int out_size)
{
    const float* x  = (const float*)d_in[0];
    const float* Wq = (const float*)d_in[1];
    const float* bq = (const float*)d_in[2];
    const float* Wk = (const float*)d_in[3];
    const float* bk = (const float*)d_in[4];
    const float* Wv = (const float*)d_in[5];
    const float* bv = (const float*)d_in[6];
    const float* Wo = (const float*)d_in[7];
    const float* bo = (const float*)d_in[8];
    float* out = (float*)d_out;

    float *q, *k, *v, *ctx;
    cudaGetSymbolAddress((void**)&q,   g_q);
    cudaGetSymbolAddress((void**)&k,   g_k);
    cudaGetSymbolAddress((void**)&v,   g_v);
    cudaGetSymbolAddress((void**)&ctx, g_ctx);

    dim3 gemm_grid(CDIM / 128, M_TOK / 128);   // (6, 128)
    sgemm_bias<<<gemm_grid, 256>>>(x, Wq, bq, q, M_TOK, CDIM, CDIM);
    sgemm_bias<<<gemm_grid, 256>>>(x, Wk, bk, k, M_TOK, CDIM, CDIM);
    sgemm_bias<<<gemm_grid, 256>>>(x, Wv, bv, v, M_TOK, CDIM, CDIM);

    const int smem = (2 * 64 * SSTR + 64 * 64) * 4;   // 51200 bytes
    static bool attr_set = false;
    if (!attr_set) {
        cudaFuncSetAttribute(attn_kernel,
                             cudaFuncAttributeMaxDynamicSharedMemorySize, smem);
        attr_set = true;
    }
    attn_kernel<<<dim3(16, 192), 256, smem>>>(q, k, v, ctx);

    sgemm_bias<<<gemm_grid, 256>>>(ctx, Wo, bo, out, M_TOK, CDIM, CDIM);
}

// round 5
// speedup vs baseline: 1.3474x; 1.3474x over previous
#include <cuda_runtime.h>
#include <cuda_bf16.h>
#include <cstdint>

// ---------------------------------------------------------------------------
// ViT self-attention. B=16, N=1024, C=768, H=12, Dh=64. M_TOK = 16384.
// Projections: mma.sync bf16 hi/lo-split GEMMs (3 terms => ~fp32 accuracy).
//   (tcgen05 is unavailable: harness ptxas target is sm_103 without 'a'.)
// Attention: fp32 flash kernel (unchanged, known-good).
// ---------------------------------------------------------------------------

#define M_TOK 16384
#define CDIM  768
#define SSTR  68

__device__ float g_q[M_TOK * CDIM];
__device__ float g_k[M_TOK * CDIM];
__device__ float g_v[M_TOK * CDIM];
__device__ float g_ctx[M_TOK * CDIM];
__device__ __nv_bfloat16 g_xh[M_TOK * CDIM];
__device__ __nv_bfloat16 g_xl[M_TOK * CDIM];
__device__ __nv_bfloat16 g_ch[M_TOK * CDIM];
__device__ __nv_bfloat16 g_cl[M_TOK * CDIM];
__device__ __nv_bfloat16 g_wqh[CDIM * CDIM];
__device__ __nv_bfloat16 g_wql[CDIM * CDIM];
__device__ __nv_bfloat16 g_wkh[CDIM * CDIM];
__device__ __nv_bfloat16 g_wkl[CDIM * CDIM];
__device__ __nv_bfloat16 g_wvh[CDIM * CDIM];
__device__ __nv_bfloat16 g_wvl[CDIM * CDIM];
__device__ __nv_bfloat16 g_woh[CDIM * CDIM];
__device__ __nv_bfloat16 g_wol[CDIM * CDIM];

// ---------------------------------------------------------------------------
// mma.sync helpers (baseline PTX, no 'a'-features)
// ---------------------------------------------------------------------------
__device__ __forceinline__ uint32_t smem_u32(const void* p) {
    uint32_t a;
    asm("{ .reg .u64 t; cvta.to.shared.u64 t, %1; cvt.u32.u64 %0, t; }"
        : "=r"(a) : "l"(p));
    return a;
}
__device__ __forceinline__ void ldsm_x4(uint32_t (&r)[4], uint32_t addr) {
    asm volatile("ldmatrix.sync.aligned.m8n8.x4.shared.b16 {%0,%1,%2,%3}, [%4];"
                 : "=r"(r[0]), "=r"(r[1]), "=r"(r[2]), "=r"(r[3]) : "r"(addr));
}
__device__ __forceinline__ void mma_bf16(float (&d)[4], const uint32_t (&a)[4],
                                         uint32_t b0, uint32_t b1) {
    asm volatile(
        "mma.sync.aligned.m16n8k16.row.col.f32.bf16.bf16.f32 "
        "{%0,%1,%2,%3}, {%4,%5,%6,%7}, {%8,%9}, {%0,%1,%2,%3};"
        : "+f"(d[0]), "+f"(d[1]), "+f"(d[2]), "+f"(d[3])
        : "r"(a[0]), "r"(a[1]), "r"(a[2]), "r"(a[3]), "r"(b0), "r"(b1));
}

// ---------------------------------------------------------------------------
// Elementwise hi/lo split: fp32 -> bf16 hi + bf16 lo
// ---------------------------------------------------------------------------
__global__ __launch_bounds__(256) void split_f32(
    const float* __restrict__ X, __nv_bfloat16* __restrict__ H,
    __nv_bfloat16* __restrict__ L, int n)
{
    int i = blockIdx.x * 256 + threadIdx.x;
    if (i < n) {
        float v = X[i];
        __nv_bfloat16 h = __float2bfloat16(v);
        H[i] = h;
        L[i] = __float2bfloat16(v - __bfloat162float(h));
    }
}

// ---------------------------------------------------------------------------
// Transpose + split W[k,n] -> Wt_hi/Wt_lo [n,k] bf16 (K-major)
// ---------------------------------------------------------------------------
__global__ __launch_bounds__(256) void transpose_split_w(
    const float* __restrict__ W, __nv_bfloat16* __restrict__ Th,
    __nv_bfloat16* __restrict__ Tl)
{
    __shared__ float tile[32][33];
    const int bx = blockIdx.x * 32;
    const int by = blockIdx.y * 32;
    const int tx = threadIdx.x, ty = threadIdx.y;  // (32, 8)
#pragma unroll
    for (int i = 0; i < 32; i += 8)
        tile[ty + i][tx] = W[(size_t)(by + ty + i) * CDIM + bx + tx];
    __syncthreads();
#pragma unroll
    for (int i = 0; i < 32; i += 8) {
        float v = tile[tx][ty + i];
        __nv_bfloat16 h = __float2bfloat16(v);
        const size_t o = (size_t)(bx + ty + i) * CDIM + by + tx;
        Th[o] = h;
        Tl[o] = __float2bfloat16(v - __bfloat162float(h));
    }
}

// ---------------------------------------------------------------------------
// bf16 split GEMM via mma.sync:
//   C[m,n] = sum_k (Ah+Al)[m,k] * (Bh+Bl)[n,k] + bias[n]   (fp32 out)
// Block tile 128x128, K-step 32, 8 warps (4m x 2n), warp tile 32x64.
// Smem row stride 40 bf16 (80B): conflict-free ldmatrix, 16B aligned.
// ---------------------------------------------------------------------------
#define KS   32
#define SST  40   // smem bf16 stride per row

__global__ __launch_bounds__(256, 1) void gemm_mma(
    const __nv_bfloat16* __restrict__ Ah, const __nv_bfloat16* __restrict__ Al,
    const __nv_bfloat16* __restrict__ Bh, const __nv_bfloat16* __restrict__ Bl,
    const float* __restrict__ bias, float* __restrict__ C)
{
    __shared__ __nv_bfloat16 sAh[128 * SST];
    __shared__ __nv_bfloat16 sAl[128 * SST];
    __shared__ __nv_bfloat16 sBh[128 * SST];
    __shared__ __nv_bfloat16 sBl[128 * SST];

    const int tid  = threadIdx.x;
    const int lane = tid & 31;
    const int wid  = tid >> 5;
    const int wm   = wid & 3;          // warp m index (0..3) -> m offset wm*32
    const int wn   = wid >> 2;         // warp n index (0..1) -> n offset wn*64
    const int m0   = blockIdx.x * 128;
    const int n0   = blockIdx.y * 128;

    const uint32_t uAh = smem_u32(sAh);
    const uint32_t uAl = smem_u32(sAl);
    const uint32_t uBh = smem_u32(sBh);
    const uint32_t uBl = smem_u32(sBl);

    const __nv_bfloat16* aH = Ah + (size_t)m0 * CDIM;
    const __nv_bfloat16* aL = Al + (size_t)m0 * CDIM;
    const __nv_bfloat16* bH = Bh + (size_t)n0 * CDIM;
    const __nv_bfloat16* bL = Bl + (size_t)n0 * CDIM;

    float acc[2][8][4];
#pragma unroll
    for (int mi = 0; mi < 2; mi++)
#pragma unroll
        for (int ni = 0; ni < 8; ni++)
#pragma unroll
            for (int r = 0; r < 4; r++) acc[mi][ni][r] = 0.0f;

    for (int kc = 0; kc < CDIM / KS; kc++) {
        const int kof = kc * KS;
        __syncthreads();
        // stage tiles: 128 rows x 32 bf16 per array; 512 uint4 per array
#pragma unroll
        for (int it = 0; it < 2; it++) {
            const int t = it * 256 + tid;       // 0..511
            const int row = t >> 2;
            const int c8  = (t & 3) * 8;        // bf16 col offset
            const size_t gof = (size_t)row * CDIM + kof + c8;
            const int so = row * SST + c8;      // bf16 offset in smem
            *(uint4*)(sAh + so) = *(const uint4*)(aH + gof);
            *(uint4*)(sAl + so) = *(const uint4*)(aL + gof);
            *(uint4*)(sBh + so) = *(const uint4*)(bH + gof);
            *(uint4*)(sBl + so) = *(const uint4*)(bL + gof);
        }
        __syncthreads();

#pragma unroll
        for (int kk2 = 0; kk2 < 2; kk2++) {
            const int kk = kk2 * 16;
            // A fragments (m16k16): addr = row (lane&15), khalf (lane>>4)
            uint32_t fah[2][4], fal[2][4];
#pragma unroll
            for (int mi = 0; mi < 2; mi++) {
                const int r = wm * 32 + mi * 16 + (lane & 15);
                const int c = kk + (lane >> 4) * 8;
                ldsm_x4(fah[mi], uAh + (uint32_t)(r * SST + c) * 2);
                ldsm_x4(fal[mi], uAl + (uint32_t)(r * SST + c) * 2);
            }
            // B fragments (n16k16 chunks): 4 chunks cover n64
            uint32_t fbh[4][4], fbl[4][4];
#pragma unroll
            for (int nc = 0; nc < 4; nc++) {
                const int r = wn * 64 + nc * 16 + (lane >> 4) * 8 + (lane & 7);
                const int c = kk + ((lane >> 3) & 1) * 8;
                ldsm_x4(fbh[nc], uBh + (uint32_t)(r * SST + c) * 2);
                ldsm_x4(fbl[nc], uBl + (uint32_t)(r * SST + c) * 2);
            }
#pragma unroll
            for (int mi = 0; mi < 2; mi++)
#pragma unroll
                for (int ni = 0; ni < 8; ni++) {
                    const int nc = ni >> 1;
                    const int p  = (ni & 1) * 2;
                    mma_bf16(acc[mi][ni], fah[mi], fbh[nc][p], fbh[nc][p + 1]);
                    mma_bf16(acc[mi][ni], fah[mi], fbl[nc][p], fbl[nc][p + 1]);
                    mma_bf16(acc[mi][ni], fal[mi], fbh[nc][p], fbh[nc][p + 1]);
                }
        }
    }

    // epilogue: d0,d1 -> (row, col..col+1); d2,d3 -> (row+8, ...)
#pragma unroll
    for (int mi = 0; mi < 2; mi++) {
        const int row = m0 + wm * 32 + mi * 16 + (lane >> 2);
#pragma unroll
        for (int ni = 0; ni < 8; ni++) {
            const int col = n0 + wn * 64 + ni * 8 + (lane & 3) * 2;
            const float b0 = bias[col], b1 = bias[col + 1];
            float2 o0 = make_float2(acc[mi][ni][0] + b0, acc[mi][ni][1] + b1);
            float2 o1 = make_float2(acc[mi][ni][2] + b0, acc[mi][ni][3] + b1);
            *(float2*)(C + (size_t)row * CDIM + col) = o0;
            *(float2*)(C + (size_t)(row + 8) * CDIM + col) = o1;
        }
    }
}

// ---------------------------------------------------------------------------
// Flash attention (fp32), unchanged from R3.
// ---------------------------------------------------------------------------
__global__ __launch_bounds__(256) void attn_kernel(
    const float* __restrict__ Q, const float* __restrict__ K,
    const float* __restrict__ V, float* __restrict__ ctx)
{
    extern __shared__ float sh[];
    float* Qst = sh;
    float* KP  = sh + 64 * SSTR;
    float* Vs  = sh + 2 * 64 * SSTR;

    const int g   = blockIdx.y;
    const int qt  = blockIdx.x;
    const int tid = threadIdx.x;
    const int tx  = tid & 15;
    const int ty  = tid >> 4;
    const float scale = 0.125f;

    const float* Qg = Q + (size_t)g * 65536 + (size_t)qt * 4096;
    const float* Kg = K + (size_t)g * 65536;
    const float* Vg = V + (size_t)g * 65536;

#pragma unroll
    for (int it = 0; it < 4; it++) {
        const int lin = it * 1024 + tid * 4;
        const int i = lin >> 6;
        const int d = lin & 63;
        float4 qv = *(const float4*)(Qg + lin);
        Qst[(d + 0) * SSTR + i] = qv.x;
        Qst[(d + 1) * SSTR + i] = qv.y;
        Qst[(d + 2) * SSTR + i] = qv.z;
        Qst[(d + 3) * SSTR + i] = qv.w;
    }

    float o[4][4];
    float m[4], l[4];
#pragma unroll
    for (int i = 0; i < 4; i++) {
        m[i] = -1e30f; l[i] = 0.0f;
#pragma unroll
        for (int j = 0; j < 4; j++) o[i][j] = 0.0f;
    }

    for (int kt = 0; kt < 16; kt++) {
        __syncthreads();
#pragma unroll
        for (int it = 0; it < 4; it++) {
            const int lin = it * 1024 + tid * 4;
            const int j = lin >> 6;
            const int d = lin & 63;
            float4 kv = *(const float4*)(Kg + kt * 4096 + lin);
            KP[(d + 0) * SSTR + j] = kv.x;
            KP[(d + 1) * SSTR + j] = kv.y;
            KP[(d + 2) * SSTR + j] = kv.z;
            KP[(d + 3) * SSTR + j] = kv.w;
            *(float4*)(Vs + lin) = *(const float4*)(Vg + kt * 4096 + lin);
        }
        __syncthreads();

        float s[4][4];
#pragma unroll
        for (int i = 0; i < 4; i++)
#pragma unroll
            for (int j = 0; j < 4; j++) s[i][j] = 0.0f;

#pragma unroll 8
        for (int d = 0; d < 64; d++) {
            float4 qv = *(float4*)&Qst[d * SSTR + ty * 4];
            float4 kv = *(float4*)&KP [d * SSTR + tx * 4];
            float ar[4] = {qv.x, qv.y, qv.z, qv.w};
            float br[4] = {kv.x, kv.y, kv.z, kv.w};
#pragma unroll
            for (int i = 0; i < 4; i++)
#pragma unroll
                for (int j = 0; j < 4; j++)
                    s[i][j] = fmaf(ar[i], br[j], s[i][j]);
        }

#pragma unroll
        for (int i = 0; i < 4; i++) {
#pragma unroll
            for (int j = 0; j < 4; j++) s[i][j] *= scale;
            float tm = fmaxf(fmaxf(s[i][0], s[i][1]), fmaxf(s[i][2], s[i][3]));
#pragma unroll
            for (int off = 8; off > 0; off >>= 1)
                tm = fmaxf(tm, __shfl_xor_sync(0xffffffffu, tm, off));
            const float nm = fmaxf(m[i], tm);
            const float f  = __expf(m[i] - nm);
            m[i] = nm;
            float rs = 0.0f;
#pragma unroll
            for (int j = 0; j < 4; j++) {
                s[i][j] = __expf(s[i][j] - nm);
                rs += s[i][j];
            }
#pragma unroll
            for (int off = 8; off > 0; off >>= 1)
                rs += __shfl_xor_sync(0xffffffffu, rs, off);
            l[i] = l[i] * f + rs;
#pragma unroll
            for (int j = 0; j < 4; j++) o[i][j] *= f;
        }

        __syncthreads();
#pragma unroll
        for (int i = 0; i < 4; i++) {
            float4 pv = make_float4(s[i][0], s[i][1], s[i][2], s[i][3]);
            *(float4*)&KP[(ty * 4 + i) * SSTR + tx * 4] = pv;
        }
        __syncthreads();

#pragma unroll 8
        for (int jj = 0; jj < 64; jj++) {
            float4 vv = *(float4*)&Vs[jj * 64 + tx * 4];
            float pv[4];
#pragma unroll
            for (int i = 0; i < 4; i++) pv[i] = KP[(ty * 4 + i) * SSTR + jj];
#pragma unroll
            for (int i = 0; i < 4; i++) {
                o[i][0] = fmaf(pv[i], vv.x, o[i][0]);
                o[i][1] = fmaf(pv[i], vv.y, o[i][1]);
                o[i][2] = fmaf(pv[i], vv.z, o[i][2]);
                o[i][3] = fmaf(pv[i], vv.w, o[i][3]);
            }
        }
    }

    const int b = g / 12;
    const int h = g % 12;
    float* outp = ctx + (size_t)b * 1024 * 768 + (size_t)(qt * 64) * 768 + h * 64;
#pragma unroll
    for (int i = 0; i < 4; i++) {
        const float inv = 1.0f / l[i];
        const int row = ty * 4 + i;
        float4 ov = make_float4(o[i][0] * inv, o[i][1] * inv,
                                o[i][2] * inv, o[i][3] * inv);
        *(float4*)(outp + (size_t)row * 768 + tx * 4) = ov;
    }
}

// ---------------------------------------------------------------------------
// Launch
// ---------------------------------------------------------------------------
extern "C" void kernel_launch(void* const* d_in, const int* in_sizes, int n_in,
                              void* d_out, int out_size)
{
    const float* x  = (const float*)d_in[0];
    const float* Wq = (const float*)d_in[1];
    const float* bq = (const float*)d_in[2];
    const float* Wk = (const float*)d_in[3];
    const float* bk = (const float*)d_in[4];
    const float* Wv = (const float*)d_in[5];
    const float* bv = (const float*)d_in[6];
    const float* Wo = (const float*)d_in[7];
    const float* bo = (const float*)d_in[8];
    float* out = (float*)d_out;

    float *q, *k, *v, *ctx;
    __nv_bfloat16 *xh, *xl, *ch, *cl;
    __nv_bfloat16 *wqh, *wql, *wkh, *wkl, *wvh, *wvl, *woh, *wol;
    cudaGetSymbolAddress((void**)&q,   g_q);
    cudaGetSymbolAddress((void**)&k,   g_k);
    cudaGetSymbolAddress((void**)&v,   g_v);
    cudaGetSymbolAddress((void**)&ctx, g_ctx);
    cudaGetSymbolAddress((void**)&xh,  g_xh);
    cudaGetSymbolAddress((void**)&xl,  g_xl);
    cudaGetSymbolAddress((void**)&ch,  g_ch);
    cudaGetSymbolAddress((void**)&cl,  g_cl);
    cudaGetSymbolAddress((void**)&wqh, g_wqh);
    cudaGetSymbolAddress((void**)&wql, g_wql);
    cudaGetSymbolAddress((void**)&wkh, g_wkh);
    cudaGetSymbolAddress((void**)&wkl, g_wkl);
    cudaGetSymbolAddress((void**)&wvh, g_wvh);
    cudaGetSymbolAddress((void**)&wvl, g_wvl);
    cudaGetSymbolAddress((void**)&woh, g_woh);
    cudaGetSymbolAddress((void**)&wol, g_wol);

    static bool attr_set = false;
    if (!attr_set) {
        cudaFuncSetAttribute(attn_kernel,
            cudaFuncAttributeMaxDynamicSharedMemorySize,
            (2 * 64 * SSTR + 64 * 64) * 4);
        attr_set = true;
    }

    const int n_act = M_TOK * CDIM;
    split_f32<<<(n_act + 255) / 256, 256>>>(x, xh, xl, n_act);

    dim3 tb(32, 8), tg(CDIM / 32, CDIM / 32);
    transpose_split_w<<<tg, tb>>>(Wq, wqh, wql);
    transpose_split_w<<<tg, tb>>>(Wk, wkh, wkl);
    transpose_split_w<<<tg, tb>>>(Wv, wvh, wvl);
    transpose_split_w<<<tg, tb>>>(Wo, woh, wol);

    dim3 ggrid(M_TOK / 128, CDIM / 128);   // (128, 6)
    gemm_mma<<<ggrid, 256>>>(xh, xl, wqh, wql, bq, q);
    gemm_mma<<<ggrid, 256>>>(xh, xl, wkh, wkl, bk, k);
    gemm_mma<<<ggrid, 256>>>(xh, xl, wvh, wvl, bv, v);

    const int asmem = (2 * 64 * SSTR + 64 * 64) * 4;
    attn_kernel<<<dim3(16, 192), 256, asmem>>>(q, k, v, ctx);

    split_f32<<<(n_act + 255) / 256, 256>>>(ctx, ch, cl, n_act);
    gemm_mma<<<ggrid, 256>>>(ch, cl, woh, wol, bo, out);
}

// round 6
// speedup vs baseline: 1.4199x; 1.0538x over previous
#include <cuda_runtime.h>
#include <cuda_bf16.h>
#include <cstdint>

// ---------------------------------------------------------------------------
// ViT self-attention. B=16, N=1024, C=768, H=12, Dh=64. M_TOK = 16384.
// Projections: mma.sync bf16 hi/lo-split GEMMs (3 terms => ~fp32 accuracy),
//   now with 2-stage cp.async double buffering.
// Attention: fp32 flash kernel (unchanged, known-good).
// ---------------------------------------------------------------------------

#define M_TOK 16384
#define CDIM  768
#define SSTR  68

__device__ float g_q[M_TOK * CDIM];
__device__ float g_k[M_TOK * CDIM];
__device__ float g_v[M_TOK * CDIM];
__device__ float g_ctx[M_TOK * CDIM];
__device__ __nv_bfloat16 g_xh[M_TOK * CDIM];
__device__ __nv_bfloat16 g_xl[M_TOK * CDIM];
__device__ __nv_bfloat16 g_ch[M_TOK * CDIM];
__device__ __nv_bfloat16 g_cl[M_TOK * CDIM];
__device__ __nv_bfloat16 g_wqh[CDIM * CDIM];
__device__ __nv_bfloat16 g_wql[CDIM * CDIM];
__device__ __nv_bfloat16 g_wkh[CDIM * CDIM];
__device__ __nv_bfloat16 g_wkl[CDIM * CDIM];
__device__ __nv_bfloat16 g_wvh[CDIM * CDIM];
__device__ __nv_bfloat16 g_wvl[CDIM * CDIM];
__device__ __nv_bfloat16 g_woh[CDIM * CDIM];
__device__ __nv_bfloat16 g_wol[CDIM * CDIM];

// ---------------------------------------------------------------------------
// PTX helpers (baseline, no 'a'-features)
// ---------------------------------------------------------------------------
__device__ __forceinline__ uint32_t smem_u32(const void* p) {
    uint32_t a;
    asm("{ .reg .u64 t; cvta.to.shared.u64 t, %1; cvt.u32.u64 %0, t; }"
        : "=r"(a) : "l"(p));
    return a;
}
__device__ __forceinline__ void ldsm_x4(uint32_t (&r)[4], uint32_t addr) {
    asm volatile("ldmatrix.sync.aligned.m8n8.x4.shared.b16 {%0,%1,%2,%3}, [%4];"
                 : "=r"(r[0]), "=r"(r[1]), "=r"(r[2]), "=r"(r[3]) : "r"(addr));
}
__device__ __forceinline__ void mma_bf16(float (&d)[4], const uint32_t (&a)[4],
                                         uint32_t b0, uint32_t b1) {
    asm volatile(
        "mma.sync.aligned.m16n8k16.row.col.f32.bf16.bf16.f32 "
        "{%0,%1,%2,%3}, {%4,%5,%6,%7}, {%8,%9}, {%0,%1,%2,%3};"
        : "+f"(d[0]), "+f"(d[1]), "+f"(d[2]), "+f"(d[3])
        : "r"(a[0]), "r"(a[1]), "r"(a[2]), "r"(a[3]), "r"(b0), "r"(b1));
}
__device__ __forceinline__ void cp16(uint32_t dst, const void* src) {
    asm volatile("cp.async.cg.shared.global [%0], [%1], 16;"
                 :: "r"(dst), "l"(src));
}
#define CP_COMMIT() asm volatile("cp.async.commit_group;" ::: "memory")
#define CP_WAIT0()  asm volatile("cp.async.wait_group 0;" ::: "memory")

// ---------------------------------------------------------------------------
// Elementwise hi/lo split: fp32 -> bf16 hi + bf16 lo
// ---------------------------------------------------------------------------
__global__ __launch_bounds__(256) void split_f32(
    const float* __restrict__ X, __nv_bfloat16* __restrict__ H,
    __nv_bfloat16* __restrict__ L, int n)
{
    int i = blockIdx.x * 256 + threadIdx.x;
    if (i < n) {
        float v = X[i];
        __nv_bfloat16 h = __float2bfloat16(v);
        H[i] = h;
        L[i] = __float2bfloat16(v - __bfloat162float(h));
    }
}

// ---------------------------------------------------------------------------
// Transpose + split W[k,n] -> Wt_hi/Wt_lo [n,k] bf16 (K-major)
// ---------------------------------------------------------------------------
__global__ __launch_bounds__(256) void transpose_split_w(
    const float* __restrict__ W, __nv_bfloat16* __restrict__ Th,
    __nv_bfloat16* __restrict__ Tl)
{
    __shared__ float tile[32][33];
    const int bx = blockIdx.x * 32;
    const int by = blockIdx.y * 32;
    const int tx = threadIdx.x, ty = threadIdx.y;  // (32, 8)
#pragma unroll
    for (int i = 0; i < 32; i += 8)
        tile[ty + i][tx] = W[(size_t)(by + ty + i) * CDIM + bx + tx];
    __syncthreads();
#pragma unroll
    for (int i = 0; i < 32; i += 8) {
        float v = tile[tx][ty + i];
        __nv_bfloat16 h = __float2bfloat16(v);
        const size_t o = (size_t)(bx + ty + i) * CDIM + by + tx;
        Th[o] = h;
        Tl[o] = __float2bfloat16(v - __bfloat162float(h));
    }
}

// ---------------------------------------------------------------------------
// bf16 split GEMM via mma.sync + 2-stage cp.async pipeline:
//   C[m,n] = sum_k (Ah+Al)[m,k] * (Bh+Bl)[n,k] + bias[n]   (fp32 out)
// Block tile 128x128, K-step 32, 8 warps (4m x 2n), warp tile 32x64.
// Smem row stride 40 bf16 (80B): conflict-free ldmatrix, 16B aligned.
// Dynamic smem: 2 stages x 4 arrays x (128*40*2)B = 81920 B.
// ---------------------------------------------------------------------------
#define KS        32
#define SST       40
#define ARR_BYTES (128 * SST * 2)        // 10240
#define STG_BYTES (4 * ARR_BYTES)        // 40960
#define GSM_TOTAL (2 * STG_BYTES)        // 81920

__global__ __launch_bounds__(256, 1) void gemm_mma(
    const __nv_bfloat16* __restrict__ Ah, const __nv_bfloat16* __restrict__ Al,
    const __nv_bfloat16* __restrict__ Bh, const __nv_bfloat16* __restrict__ Bl,
    const float* __restrict__ bias, float* __restrict__ C)
{
    extern __shared__ char gsm[];
    const uint32_t sb = smem_u32(gsm);

    const int tid  = threadIdx.x;
    const int lane = tid & 31;
    const int wid  = tid >> 5;
    const int wm   = wid & 3;
    const int wn   = wid >> 2;
    const int m0   = blockIdx.x * 128;
    const int n0   = blockIdx.y * 128;

    const __nv_bfloat16* aH = Ah + (size_t)m0 * CDIM;
    const __nv_bfloat16* aL = Al + (size_t)m0 * CDIM;
    const __nv_bfloat16* bH = Bh + (size_t)n0 * CDIM;
    const __nv_bfloat16* bL = Bl + (size_t)n0 * CDIM;

    float acc[2][8][4];
#pragma unroll
    for (int mi = 0; mi < 2; mi++)
#pragma unroll
        for (int ni = 0; ni < 8; ni++)
#pragma unroll
            for (int r = 0; r < 4; r++) acc[mi][ni][r] = 0.0f;

    // staging: each thread issues 8 x 16B cp.async per stage
    auto issue = [&](int kc, int stg) {
        const int kof = kc * KS;
        const uint32_t base = sb + stg * STG_BYTES;
#pragma unroll
        for (int it = 0; it < 2; it++) {
            const int t = it * 256 + tid;       // 0..511
            const int row = t >> 2;
            const int c8  = (t & 3) * 8;
            const size_t gof = (size_t)row * CDIM + kof + c8;
            const uint32_t so = base + (uint32_t)(row * SST + c8) * 2;
            cp16(so + 0 * ARR_BYTES, aH + gof);
            cp16(so + 1 * ARR_BYTES, aL + gof);
            cp16(so + 2 * ARR_BYTES, bH + gof);
            cp16(so + 3 * ARR_BYTES, bL + gof);
        }
    };

    issue(0, 0);
    CP_COMMIT();

    int buf = 0;
    for (int kc = 0; kc < CDIM / KS; kc++) {
        CP_WAIT0();
        __syncthreads();
        if (kc + 1 < CDIM / KS) {
            issue(kc + 1, buf ^ 1);
            CP_COMMIT();
        }

        const uint32_t uAh = sb + buf * STG_BYTES + 0 * ARR_BYTES;
        const uint32_t uAl = uAh + ARR_BYTES;
        const uint32_t uBh = uAh + 2 * ARR_BYTES;
        const uint32_t uBl = uAh + 3 * ARR_BYTES;

#pragma unroll
        for (int kk2 = 0; kk2 < 2; kk2++) {
            const int kk = kk2 * 16;
            uint32_t fah[2][4], fal[2][4];
#pragma unroll
            for (int mi = 0; mi < 2; mi++) {
                const int r = wm * 32 + mi * 16 + (lane & 15);
                const int c = kk + (lane >> 4) * 8;
                ldsm_x4(fah[mi], uAh + (uint32_t)(r * SST + c) * 2);
                ldsm_x4(fal[mi], uAl + (uint32_t)(r * SST + c) * 2);
            }
            uint32_t fbh[4][4], fbl[4][4];
#pragma unroll
            for (int nc = 0; nc < 4; nc++) {
                const int r = wn * 64 + nc * 16 + (lane >> 4) * 8 + (lane & 7);
                const int c = kk + ((lane >> 3) & 1) * 8;
                ldsm_x4(fbh[nc], uBh + (uint32_t)(r * SST + c) * 2);
                ldsm_x4(fbl[nc], uBl + (uint32_t)(r * SST + c) * 2);
            }
#pragma unroll
            for (int mi = 0; mi < 2; mi++)
#pragma unroll
                for (int ni = 0; ni < 8; ni++) {
                    const int nc = ni >> 1;
                    const int p  = (ni & 1) * 2;
                    mma_bf16(acc[mi][ni], fah[mi], fbh[nc][p], fbh[nc][p + 1]);
                    mma_bf16(acc[mi][ni], fah[mi], fbl[nc][p], fbl[nc][p + 1]);
                    mma_bf16(acc[mi][ni], fal[mi], fbh[nc][p], fbh[nc][p + 1]);
                }
        }
        buf ^= 1;
        __syncthreads();
    }

    // epilogue
#pragma unroll
    for (int mi = 0; mi < 2; mi++) {
        const int row = m0 + wm * 32 + mi * 16 + (lane >> 2);
#pragma unroll
        for (int ni = 0; ni < 8; ni++) {
            const int col = n0 + wn * 64 + ni * 8 + (lane & 3) * 2;
            const float b0 = bias[col], b1 = bias[col + 1];
            float2 o0 = make_float2(acc[mi][ni][0] + b0, acc[mi][ni][1] + b1);
            float2 o1 = make_float2(acc[mi][ni][2] + b0, acc[mi][ni][3] + b1);
            *(float2*)(C + (size_t)row * CDIM + col) = o0;
            *(float2*)(C + (size_t)(row + 8) * CDIM + col) = o1;
        }
    }
}

// ---------------------------------------------------------------------------
// Flash attention (fp32), unchanged.
// ---------------------------------------------------------------------------
__global__ __launch_bounds__(256) void attn_kernel(
    const float* __restrict__ Q, const float* __restrict__ K,
    const float* __restrict__ V, float* __restrict__ ctx)
{
    extern __shared__ float sh[];
    float* Qst = sh;
    float* KP  = sh + 64 * SSTR;
    float* Vs  = sh + 2 * 64 * SSTR;

    const int g   = blockIdx.y;
    const int qt  = blockIdx.x;
    const int tid = threadIdx.x;
    const int tx  = tid & 15;
    const int ty  = tid >> 4;
    const float scale = 0.125f;

    const float* Qg = Q + (size_t)g * 65536 + (size_t)qt * 4096;
    const float* Kg = K + (size_t)g * 65536;
    const float* Vg = V + (size_t)g * 65536;

#pragma unroll
    for (int it = 0; it < 4; it++) {
        const int lin = it * 1024 + tid * 4;
        const int i = lin >> 6;
        const int d = lin & 63;
        float4 qv = *(const float4*)(Qg + lin);
        Qst[(d + 0) * SSTR + i] = qv.x;
        Qst[(d + 1) * SSTR + i] = qv.y;
        Qst[(d + 2) * SSTR + i] = qv.z;
        Qst[(d + 3) * SSTR + i] = qv.w;
    }

    float o[4][4];
    float m[4], l[4];
#pragma unroll
    for (int i = 0; i < 4; i++) {
        m[i] = -1e30f; l[i] = 0.0f;
#pragma unroll
        for (int j = 0; j < 4; j++) o[i][j] = 0.0f;
    }

    for (int kt = 0; kt < 16; kt++) {
        __syncthreads();
#pragma unroll
        for (int it = 0; it < 4; it++) {
            const int lin = it * 1024 + tid * 4;
            const int j = lin >> 6;
            const int d = lin & 63;
            float4 kv = *(const float4*)(Kg + kt * 4096 + lin);
            KP[(d + 0) * SSTR + j] = kv.x;
            KP[(d + 1) * SSTR + j] = kv.y;
            KP[(d + 2) * SSTR + j] = kv.z;
            KP[(d + 3) * SSTR + j] = kv.w;
            *(float4*)(Vs + lin) = *(const float4*)(Vg + kt * 4096 + lin);
        }
        __syncthreads();

        float s[4][4];
#pragma unroll
        for (int i = 0; i < 4; i++)
#pragma unroll
            for (int j = 0; j < 4; j++) s[i][j] = 0.0f;

#pragma unroll 8
        for (int d = 0; d < 64; d++) {
            float4 qv = *(float4*)&Qst[d * SSTR + ty * 4];
            float4 kv = *(float4*)&KP [d * SSTR + tx * 4];
            float ar[4] = {qv.x, qv.y, qv.z, qv.w};
            float br[4] = {kv.x, kv.y, kv.z, kv.w};
#pragma unroll
            for (int i = 0; i < 4; i++)
#pragma unroll
                for (int j = 0; j < 4; j++)
                    s[i][j] = fmaf(ar[i], br[j], s[i][j]);
        }

#pragma unroll
        for (int i = 0; i < 4; i++) {
#pragma unroll
            for (int j = 0; j < 4; j++) s[i][j] *= scale;
            float tm = fmaxf(fmaxf(s[i][0], s[i][1]), fmaxf(s[i][2], s[i][3]));
#pragma unroll
            for (int off = 8; off > 0; off >>= 1)
                tm = fmaxf(tm, __shfl_xor_sync(0xffffffffu, tm, off));
            const float nm = fmaxf(m[i], tm);
            const float f  = __expf(m[i] - nm);
            m[i] = nm;
            float rs = 0.0f;
#pragma unroll
            for (int j = 0; j < 4; j++) {
                s[i][j] = __expf(s[i][j] - nm);
                rs += s[i][j];
            }
#pragma unroll
            for (int off = 8; off > 0; off >>= 1)
                rs += __shfl_xor_sync(0xffffffffu, rs, off);
            l[i] = l[i] * f + rs;
#pragma unroll
            for (int j = 0; j < 4; j++) o[i][j] *= f;
        }

        __syncthreads();
#pragma unroll
        for (int i = 0; i < 4; i++) {
            float4 pv = make_float4(s[i][0], s[i][1], s[i][2], s[i][3]);
            *(float4*)&KP[(ty * 4 + i) * SSTR + tx * 4] = pv;
        }
        __syncthreads();

#pragma unroll 8
        for (int jj = 0; jj < 64; jj++) {
            float4 vv = *(float4*)&Vs[jj * 64 + tx * 4];
            float pv[4];
#pragma unroll
            for (int i = 0; i < 4; i++) pv[i] = KP[(ty * 4 + i) * SSTR + jj];
#pragma unroll
            for (int i = 0; i < 4; i++) {
                o[i][0] = fmaf(pv[i], vv.x, o[i][0]);
                o[i][1] = fmaf(pv[i], vv.y, o[i][1]);
                o[i][2] = fmaf(pv[i], vv.z, o[i][2]);
                o[i][3] = fmaf(pv[i], vv.w, o[i][3]);
            }
        }
    }

    const int b = g / 12;
    const int h = g % 12;
    float* outp = ctx + (size_t)b * 1024 * 768 + (size_t)(qt * 64) * 768 + h * 64;
#pragma unroll
    for (int i = 0; i < 4; i++) {
        const float inv = 1.0f / l[i];
        const int row = ty * 4 + i;
        float4 ov = make_float4(o[i][0] * inv, o[i][1] * inv,
                                o[i][2] * inv, o[i][3] * inv);
        *(float4*)(outp + (size_t)row * 768 + tx * 4) = ov;
    }
}

// ---------------------------------------------------------------------------
// Launch
// ---------------------------------------------------------------------------
extern "C" void kernel_launch(void* const* d_in, const int* in_sizes, int n_in,
                              void* d_out, int out_size)
{
    const float* x  = (const float*)d_in[0];
    const float* Wq = (const float*)d_in[1];
    const float* bq = (const float*)d_in[2];
    const float* Wk = (const float*)d_in[3];
    const float* bk = (const float*)d_in[4];
    const float* Wv = (const float*)d_in[5];
    const float* bv = (const float*)d_in[6];
    const float* Wo = (const float*)d_in[7];
    const float* bo = (const float*)d_in[8];
    float* out = (float*)d_out;

    float *q, *k, *v, *ctx;
    __nv_bfloat16 *xh, *xl, *ch, *cl;
    __nv_bfloat16 *wqh, *wql, *wkh, *wkl, *wvh, *wvl, *woh, *wol;
    cudaGetSymbolAddress((void**)&q,   g_q);
    cudaGetSymbolAddress((void**)&k,   g_k);
    cudaGetSymbolAddress((void**)&v,   g_v);
    cudaGetSymbolAddress((void**)&ctx, g_ctx);
    cudaGetSymbolAddress((void**)&xh,  g_xh);
    cudaGetSymbolAddress((void**)&xl,  g_xl);
    cudaGetSymbolAddress((void**)&ch,  g_ch);
    cudaGetSymbolAddress((void**)&cl,  g_cl);
    cudaGetSymbolAddress((void**)&wqh, g_wqh);
    cudaGetSymbolAddress((void**)&wql, g_wql);
    cudaGetSymbolAddress((void**)&wkh, g_wkh);
    cudaGetSymbolAddress((void**)&wkl, g_wkl);
    cudaGetSymbolAddress((void**)&wvh, g_wvh);
    cudaGetSymbolAddress((void**)&wvl, g_wvl);
    cudaGetSymbolAddress((void**)&woh, g_woh);
    cudaGetSymbolAddress((void**)&wol, g_wol);

    static bool attr_set = false;
    if (!attr_set) {
        cudaFuncSetAttribute(gemm_mma,
            cudaFuncAttributeMaxDynamicSharedMemorySize, GSM_TOTAL);
        cudaFuncSetAttribute(attn_kernel,
            cudaFuncAttributeMaxDynamicSharedMemorySize,
            (2 * 64 * SSTR + 64 * 64) * 4);
        attr_set = true;
    }

    const int n_act = M_TOK * CDIM;
    split_f32<<<(n_act + 255) / 256, 256>>>(x, xh, xl, n_act);

    dim3 tb(32, 8), tg(CDIM / 32, CDIM / 32);
    transpose_split_w<<<tg, tb>>>(Wq, wqh, wql);
    transpose_split_w<<<tg, tb>>>(Wk, wkh, wkl);
    transpose_split_w<<<tg, tb>>>(Wv, wvh, wvl);
    transpose_split_w<<<tg, tb>>>(Wo, woh, wol);

    dim3 ggrid(M_TOK / 128, CDIM / 128);   // (128, 6)
    gemm_mma<<<ggrid, 256, GSM_TOTAL>>>(xh, xl, wqh, wql, bq, q);
    gemm_mma<<<ggrid, 256, GSM_TOTAL>>>(xh, xl, wkh, wkl, bk, k);
    gemm_mma<<<ggrid, 256, GSM_TOTAL>>>(xh, xl, wvh, wvl, bv, v);

    const int asmem = (2 * 64 * SSTR + 64 * 64) * 4;
    attn_kernel<<<dim3(16, 192), 256, asmem>>>(q, k, v, ctx);

    split_f32<<<(n_act + 255) / 256, 256>>>(ctx, ch, cl, n_act);
    gemm_mma<<<ggrid, 256, GSM_TOTAL>>>(ch, cl, woh, wol, bo, out);
}

// round 8
// speedup vs baseline: 2.2556x; 1.5886x over previous
#include <cuda_runtime.h>
#include <cuda_bf16.h>
#include <cstdint>

// ---------------------------------------------------------------------------
// ViT self-attention. B=16, N=1024, C=768, H=12, Dh=64. M_TOK = 16384.
// Projections: mma.sync bf16 hi/lo-split GEMMs (3 terms), cp.async pipelined,
//   emitting bf16 hi/lo outputs directly for q,k,v.
// Attention: tensor-core flash attention. S: Qh/Ql x Kh/Kl (3 terms).
//   P split hi/lo; O += Ph*Vh + Pl*Vh + Ph*Vl (3 terms). Emits bf16 hi/lo ctx.
// Final projection: same GEMM, fp32 output.
// ---------------------------------------------------------------------------

#define M_TOK 16384
#define CDIM  768

__device__ __nv_bfloat16 g_xh[M_TOK * CDIM];
__device__ __nv_bfloat16 g_xl[M_TOK * CDIM];
__device__ __nv_bfloat16 g_qh[M_TOK * CDIM];
__device__ __nv_bfloat16 g_ql[M_TOK * CDIM];
__device__ __nv_bfloat16 g_kh[M_TOK * CDIM];
__device__ __nv_bfloat16 g_kl[M_TOK * CDIM];
__device__ __nv_bfloat16 g_vh[M_TOK * CDIM];
__device__ __nv_bfloat16 g_vl[M_TOK * CDIM];
__device__ __nv_bfloat16 g_ch[M_TOK * CDIM];
__device__ __nv_bfloat16 g_cl[M_TOK * CDIM];
__device__ __nv_bfloat16 g_wqh[CDIM * CDIM];
__device__ __nv_bfloat16 g_wql[CDIM * CDIM];
__device__ __nv_bfloat16 g_wkh[CDIM * CDIM];
__device__ __nv_bfloat16 g_wkl[CDIM * CDIM];
__device__ __nv_bfloat16 g_wvh[CDIM * CDIM];
__device__ __nv_bfloat16 g_wvl[CDIM * CDIM];
__device__ __nv_bfloat16 g_woh[CDIM * CDIM];
__device__ __nv_bfloat16 g_wol[CDIM * CDIM];

// ---------------------------------------------------------------------------
// PTX helpers (baseline, no 'a'-features)
// ---------------------------------------------------------------------------
__device__ __forceinline__ uint32_t smem_u32(const void* p) {
    uint32_t a;
    asm("{ .reg .u64 t; cvta.to.shared.u64 t, %1; cvt.u32.u64 %0, t; }"
        : "=r"(a) : "l"(p));
    return a;
}
__device__ __forceinline__ void ldsm_x4(uint32_t (&r)[4], uint32_t addr) {
    asm volatile("ldmatrix.sync.aligned.m8n8.x4.shared.b16 {%0,%1,%2,%3}, [%4];"
                 : "=r"(r[0]), "=r"(r[1]), "=r"(r[2]), "=r"(r[3]) : "r"(addr));
}
__device__ __forceinline__ void ldsm_x4_t(uint32_t (&r)[4], uint32_t addr) {
    asm volatile("ldmatrix.sync.aligned.m8n8.x4.trans.shared.b16 {%0,%1,%2,%3}, [%4];"
                 : "=r"(r[0]), "=r"(r[1]), "=r"(r[2]), "=r"(r[3]) : "r"(addr));
}
__device__ __forceinline__ void mma_bf16(float (&d)[4], const uint32_t (&a)[4],
                                         uint32_t b0, uint32_t b1) {
    asm volatile(
        "mma.sync.aligned.m16n8k16.row.col.f32.bf16.bf16.f32 "
        "{%0,%1,%2,%3}, {%4,%5,%6,%7}, {%8,%9}, {%0,%1,%2,%3};"
        : "+f"(d[0]), "+f"(d[1]), "+f"(d[2]), "+f"(d[3])
        : "r"(a[0]), "r"(a[1]), "r"(a[2]), "r"(a[3]), "r"(b0), "r"(b1));
}
__device__ __forceinline__ void cp16(uint32_t dst, const void* src) {
    asm volatile("cp.async.cg.shared.global [%0], [%1], 16;"
                 :: "r"(dst), "l"(src));
}
#define CP_COMMIT() asm volatile("cp.async.commit_group;" ::: "memory")
#define CP_WAIT0()  asm volatile("cp.async.wait_group 0;" ::: "memory")

__device__ __forceinline__ void split_pair(float a, float b,
                                           uint32_t& hi, uint32_t& lo) {
    __nv_bfloat16 ha = __float2bfloat16(a);
    __nv_bfloat16 hb = __float2bfloat16(b);
    __nv_bfloat162 h2; h2.x = ha; h2.y = hb;
    __nv_bfloat162 l2;
    l2.x = __float2bfloat16(a - __bfloat162float(ha));
    l2.y = __float2bfloat16(b - __bfloat162float(hb));
    hi = *reinterpret_cast<uint32_t*>(&h2);
    lo = *reinterpret_cast<uint32_t*>(&l2);
}

// ---------------------------------------------------------------------------
// Elementwise hi/lo split (input x only)
// ---------------------------------------------------------------------------
__global__ __launch_bounds__(256) void split_f32(
    const float* __restrict__ X, __nv_bfloat16* __restrict__ H,
    __nv_bfloat16* __restrict__ L, int n)
{
    int i = blockIdx.x * 256 + threadIdx.x;
    if (i < n) {
        float v = X[i];
        __nv_bfloat16 h = __float2bfloat16(v);
        H[i] = h;
        L[i] = __float2bfloat16(v - __bfloat162float(h));
    }
}

// ---------------------------------------------------------------------------
// Transpose + split W[k,n] -> Wt_hi/Wt_lo [n,k] bf16
// ---------------------------------------------------------------------------
__global__ __launch_bounds__(256) void transpose_split_w(
    const float* __restrict__ W, __nv_bfloat16* __restrict__ Th,
    __nv_bfloat16* __restrict__ Tl)
{
    __shared__ float tile[32][33];
    const int bx = blockIdx.x * 32;
    const int by = blockIdx.y * 32;
    const int tx = threadIdx.x, ty = threadIdx.y;
#pragma unroll
    for (int i = 0; i < 32; i += 8)
        tile[ty + i][tx] = W[(size_t)(by + ty + i) * CDIM + bx + tx];
    __syncthreads();
#pragma unroll
    for (int i = 0; i < 32; i += 8) {
        float v = tile[tx][ty + i];
        __nv_bfloat16 h = __float2bfloat16(v);
        const size_t o = (size_t)(bx + ty + i) * CDIM + by + tx;
        Th[o] = h;
        Tl[o] = __float2bfloat16(v - __bfloat162float(h));
    }
}

// ---------------------------------------------------------------------------
// bf16 split GEMM (mma.sync + 2-stage cp.async). Epilogue: fp32 OR bf16 hi/lo.
// ---------------------------------------------------------------------------
#define KS        32
#define SST       40
#define ARR_BYTES (128 * SST * 2)
#define STG_BYTES (4 * ARR_BYTES)
#define GSM_TOTAL (2 * STG_BYTES)

__global__ __launch_bounds__(256, 1) void gemm_mma(
    const __nv_bfloat16* __restrict__ Ah, const __nv_bfloat16* __restrict__ Al,
    const __nv_bfloat16* __restrict__ Bh, const __nv_bfloat16* __restrict__ Bl,
    const float* __restrict__ bias, float* __restrict__ Cf,
    __nv_bfloat16* __restrict__ Ch, __nv_bfloat16* __restrict__ Cl)
{
    extern __shared__ char gsm[];
    const uint32_t sb = smem_u32(gsm);

    const int tid  = threadIdx.x;
    const int lane = tid & 31;
    const int wid  = tid >> 5;
    const int wm   = wid & 3;
    const int wn   = wid >> 2;
    const int m0   = blockIdx.x * 128;
    const int n0   = blockIdx.y * 128;

    const __nv_bfloat16* aH = Ah + (size_t)m0 * CDIM;
    const __nv_bfloat16* aL = Al + (size_t)m0 * CDIM;
    const __nv_bfloat16* bH = Bh + (size_t)n0 * CDIM;
    const __nv_bfloat16* bL = Bl + (size_t)n0 * CDIM;

    float acc[2][8][4];
#pragma unroll
    for (int mi = 0; mi < 2; mi++)
#pragma unroll
        for (int ni = 0; ni < 8; ni++)
#pragma unroll
            for (int r = 0; r < 4; r++) acc[mi][ni][r] = 0.0f;

    auto issue = [&](int kc, int stg) {
        const int kof = kc * KS;
        const uint32_t base = sb + stg * STG_BYTES;
#pragma unroll
        for (int it = 0; it < 2; it++) {
            const int t = it * 256 + tid;
            const int row = t >> 2;
            const int c8  = (t & 3) * 8;
            const size_t gof = (size_t)row * CDIM + kof + c8;
            const uint32_t so = base + (uint32_t)(row * SST + c8) * 2;
            cp16(so + 0 * ARR_BYTES, aH + gof);
            cp16(so + 1 * ARR_BYTES, aL + gof);
            cp16(so + 2 * ARR_BYTES, bH + gof);
            cp16(so + 3 * ARR_BYTES, bL + gof);
        }
    };

    issue(0, 0);
    CP_COMMIT();

    int buf = 0;
    for (int kc = 0; kc < CDIM / KS; kc++) {
        CP_WAIT0();
        __syncthreads();
        if (kc + 1 < CDIM / KS) {
            issue(kc + 1, buf ^ 1);
            CP_COMMIT();
        }

        const uint32_t uAh = sb + buf * STG_BYTES;
        const uint32_t uAl = uAh + ARR_BYTES;
        const uint32_t uBh = uAh + 2 * ARR_BYTES;
        const uint32_t uBl = uAh + 3 * ARR_BYTES;

#pragma unroll
        for (int kk2 = 0; kk2 < 2; kk2++) {
            const int kk = kk2 * 16;
            uint32_t fah[2][4], fal[2][4];
#pragma unroll
            for (int mi = 0; mi < 2; mi++) {
                const int r = wm * 32 + mi * 16 + (lane & 15);
                const int c = kk + (lane >> 4) * 8;
                ldsm_x4(fah[mi], uAh + (uint32_t)(r * SST + c) * 2);
                ldsm_x4(fal[mi], uAl + (uint32_t)(r * SST + c) * 2);
            }
            uint32_t fbh[4][4], fbl[4][4];
#pragma unroll
            for (int nc = 0; nc < 4; nc++) {
                const int r = wn * 64 + nc * 16 + (lane >> 4) * 8 + (lane & 7);
                const int c = kk + ((lane >> 3) & 1) * 8;
                ldsm_x4(fbh[nc], uBh + (uint32_t)(r * SST + c) * 2);
                ldsm_x4(fbl[nc], uBl + (uint32_t)(r * SST + c) * 2);
            }
#pragma unroll
            for (int mi = 0; mi < 2; mi++)
#pragma unroll
                for (int ni = 0; ni < 8; ni++) {
                    const int nc = ni >> 1;
                    const int p  = (ni & 1) * 2;
                    mma_bf16(acc[mi][ni], fah[mi], fbh[nc][p], fbh[nc][p + 1]);
                    mma_bf16(acc[mi][ni], fah[mi], fbl[nc][p], fbl[nc][p + 1]);
                    mma_bf16(acc[mi][ni], fal[mi], fbh[nc][p], fbh[nc][p + 1]);
                }
        }
        buf ^= 1;
        __syncthreads();
    }

#pragma unroll
    for (int mi = 0; mi < 2; mi++) {
        const int row = m0 + wm * 32 + mi * 16 + (lane >> 2);
#pragma unroll
        for (int ni = 0; ni < 8; ni++) {
            const int col = n0 + wn * 64 + ni * 8 + (lane & 3) * 2;
            const float b0 = bias[col], b1 = bias[col + 1];
            const float v00 = acc[mi][ni][0] + b0, v01 = acc[mi][ni][1] + b1;
            const float v10 = acc[mi][ni][2] + b0, v11 = acc[mi][ni][3] + b1;
            if (Cf) {
                *(float2*)(Cf + (size_t)row * CDIM + col) = make_float2(v00, v01);
                *(float2*)(Cf + (size_t)(row + 8) * CDIM + col) = make_float2(v10, v11);
            } else {
                uint32_t h0, l0, h1, l1;
                split_pair(v00, v01, h0, l0);
                split_pair(v10, v11, h1, l1);
                *(uint32_t*)(Ch + (size_t)row * CDIM + col) = h0;
                *(uint32_t*)(Cl + (size_t)row * CDIM + col) = l0;
                *(uint32_t*)(Ch + (size_t)(row + 8) * CDIM + col) = h1;
                *(uint32_t*)(Cl + (size_t)(row + 8) * CDIM + col) = l1;
            }
        }
    }
}

// ---------------------------------------------------------------------------
// Tensor-core flash attention over 192 contiguous (1024 x 64) groups.
// Block: 256 thr (8 warps), q-tile 128 rows (warp = 16 rows), kt tiles of 64.
// S = (Qh+Ql)(Kh+Kl)^T (3 terms). P split hi/lo.
// O += Ph Vh + Pl Vh + Ph Vl (3 terms).
// smem: Qh/Ql [128][AST], Kh/Kl/Vh/Vl [64][AST] bf16. AST=72 (144B rows).
// ---------------------------------------------------------------------------
#define AST 72
#define A_QH 0
#define A_QL (128 * AST * 2)            // 18432
#define A_KH (2 * 128 * AST * 2)        // 36864
#define A_KL (A_KH + 64 * AST * 2)
#define A_VH (A_KH + 2 * 64 * AST * 2)
#define A_VL (A_KH + 3 * 64 * AST * 2)
#define ASM_TOTAL (A_KH + 4 * 64 * AST * 2)   // 73728

__global__ __launch_bounds__(256, 1) void attn_tc(
    const __nv_bfloat16* __restrict__ Qh, const __nv_bfloat16* __restrict__ Ql,
    const __nv_bfloat16* __restrict__ Kh, const __nv_bfloat16* __restrict__ Kl,
    const __nv_bfloat16* __restrict__ Vh, const __nv_bfloat16* __restrict__ Vl,
    __nv_bfloat16* __restrict__ Ch, __nv_bfloat16* __restrict__ Cl)
{
    extern __shared__ char asm_[];
    const uint32_t sb = smem_u32(asm_);

    const int g    = blockIdx.y;
    const int qt   = blockIdx.x;
    const int tid  = threadIdx.x;
    const int lane = tid & 31;
    const int w    = tid >> 5;
    const int gr   = lane >> 2;
    const int gc   = (lane & 3) * 2;

    const size_t gof = (size_t)g * 65536;
    const __nv_bfloat16* qHg = Qh + gof + (size_t)qt * 8192;
    const __nv_bfloat16* qLg = Ql + gof + (size_t)qt * 8192;
    const __nv_bfloat16* kHg = Kh + gof;
    const __nv_bfloat16* kLg = Kl + gof;
    const __nv_bfloat16* vHg = Vh + gof;
    const __nv_bfloat16* vLg = Vl + gof;

    // stage Q (128 x 64 hi/lo)
#pragma unroll
    for (int it = 0; it < 4; it++) {
        const int idx = it * 256 + tid;
        const int row = idx >> 3;
        const int c16 = idx & 7;
        const uint32_t so = sb + (uint32_t)(row * AST + c16 * 8) * 2;
        cp16(so + A_QH, qHg + row * 64 + c16 * 8);
        cp16(so + A_QL, qLg + row * 64 + c16 * 8);
    }
    CP_COMMIT();
    CP_WAIT0();
    __syncthreads();

    uint32_t fqh[4][4], fql[4][4];
#pragma unroll
    for (int kc = 0; kc < 4; kc++) {
        const int r = w * 16 + (lane & 15);
        const int c = kc * 16 + (lane >> 4) * 8;
        ldsm_x4(fqh[kc], sb + A_QH + (uint32_t)(r * AST + c) * 2);
        ldsm_x4(fql[kc], sb + A_QL + (uint32_t)(r * AST + c) * 2);
    }

    float acc_o[8][4];
#pragma unroll
    for (int ni = 0; ni < 8; ni++)
#pragma unroll
        for (int r = 0; r < 4; r++) acc_o[ni][r] = 0.0f;
    float m0 = -1e30f, m1 = -1e30f, l0 = 0.0f, l1 = 0.0f;
    const float scale = 0.125f;

    for (int kt = 0; kt < 16; kt++) {
        __syncthreads();
#pragma unroll
        for (int it = 0; it < 2; it++) {
            const int idx = it * 256 + tid;
            const int row = idx >> 3;
            const int c16 = idx & 7;
            const size_t go = (size_t)(kt * 64 + row) * 64 + c16 * 8;
            const uint32_t so = sb + (uint32_t)(row * AST + c16 * 8) * 2;
            cp16(so + A_KH, kHg + go);
            cp16(so + A_KL, kLg + go);
            cp16(so + A_VH, vHg + go);
            cp16(so + A_VL, vLg + go);
        }
        CP_COMMIT();
        CP_WAIT0();
        __syncthreads();

        // S = Q K^T  (16 x 64 per warp), 3 split terms
        float s[8][4];
#pragma unroll
        for (int ni = 0; ni < 8; ni++)
#pragma unroll
            for (int r = 0; r < 4; r++) s[ni][r] = 0.0f;

#pragma unroll
        for (int n16 = 0; n16 < 4; n16++) {
            const int r = n16 * 16 + (lane >> 4) * 8 + (lane & 7);
            const int rr = ((lane >> 3) & 1) * 8;
#pragma unroll
            for (int kc = 0; kc < 4; kc++) {
                uint32_t kh4[4], kl4[4];
                const int c = kc * 16 + rr;
                ldsm_x4(kh4, sb + A_KH + (uint32_t)(r * AST + c) * 2);
                ldsm_x4(kl4, sb + A_KL + (uint32_t)(r * AST + c) * 2);
                mma_bf16(s[2 * n16 + 0], fqh[kc], kh4[0], kh4[1]);
                mma_bf16(s[2 * n16 + 1], fqh[kc], kh4[2], kh4[3]);
                mma_bf16(s[2 * n16 + 0], fqh[kc], kl4[0], kl4[1]);
                mma_bf16(s[2 * n16 + 1], fqh[kc], kl4[2], kl4[3]);
                mma_bf16(s[2 * n16 + 0], fql[kc], kh4[0], kh4[1]);
                mma_bf16(s[2 * n16 + 1], fql[kc], kh4[2], kh4[3]);
            }
        }

        // online softmax
        float tm0 = -1e30f, tm1 = -1e30f;
#pragma unroll
        for (int ni = 0; ni < 8; ni++) {
            s[ni][0] *= scale; s[ni][1] *= scale;
            s[ni][2] *= scale; s[ni][3] *= scale;
            tm0 = fmaxf(tm0, fmaxf(s[ni][0], s[ni][1]));
            tm1 = fmaxf(tm1, fmaxf(s[ni][2], s[ni][3]));
        }
        tm0 = fmaxf(tm0, __shfl_xor_sync(0xffffffffu, tm0, 1));
        tm0 = fmaxf(tm0, __shfl_xor_sync(0xffffffffu, tm0, 2));
        tm1 = fmaxf(tm1, __shfl_xor_sync(0xffffffffu, tm1, 1));
        tm1 = fmaxf(tm1, __shfl_xor_sync(0xffffffffu, tm1, 2));
        const float nm0 = fmaxf(m0, tm0);
        const float nm1 = fmaxf(m1, tm1);
        const float f0 = __expf(m0 - nm0);
        const float f1 = __expf(m1 - nm1);
        m0 = nm0; m1 = nm1;

        float rs0 = 0.0f, rs1 = 0.0f;
#pragma unroll
        for (int ni = 0; ni < 8; ni++) {
            s[ni][0] = __expf(s[ni][0] - nm0);
            s[ni][1] = __expf(s[ni][1] - nm0);
            s[ni][2] = __expf(s[ni][2] - nm1);
            s[ni][3] = __expf(s[ni][3] - nm1);
            rs0 += s[ni][0] + s[ni][1];
            rs1 += s[ni][2] + s[ni][3];
        }
        rs0 += __shfl_xor_sync(0xffffffffu, rs0, 1);
        rs0 += __shfl_xor_sync(0xffffffffu, rs0, 2);
        rs1 += __shfl_xor_sync(0xffffffffu, rs1, 1);
        rs1 += __shfl_xor_sync(0xffffffffu, rs1, 2);
        l0 = l0 * f0 + rs0;
        l1 = l1 * f1 + rs1;

        // P hi/lo fragments (A-operand layout for the PV mma)
        uint32_t pah[4][4], pal[4][4];
#pragma unroll
        for (int kc = 0; kc < 4; kc++) {
            split_pair(s[2 * kc][0],     s[2 * kc][1],     pah[kc][0], pal[kc][0]);
            split_pair(s[2 * kc][2],     s[2 * kc][3],     pah[kc][1], pal[kc][1]);
            split_pair(s[2 * kc + 1][0], s[2 * kc + 1][1], pah[kc][2], pal[kc][2]);
            split_pair(s[2 * kc + 1][2], s[2 * kc + 1][3], pah[kc][3], pal[kc][3]);
        }
#pragma unroll
        for (int ni = 0; ni < 8; ni++) {
            acc_o[ni][0] *= f0; acc_o[ni][1] *= f0;
            acc_o[ni][2] *= f1; acc_o[ni][3] *= f1;
        }

        // O += Ph Vh + Pl Vh + Ph Vl
#pragma unroll
        for (int kc = 0; kc < 4; kc++) {
            const int r = kc * 16 + (lane & 15);
            const int rr = (lane >> 4) * 8;
#pragma unroll
            for (int nd = 0; nd < 4; nd++) {
                uint32_t vh4[4], vl4[4];
                const int c = nd * 16 + rr;
                ldsm_x4_t(vh4, sb + A_VH + (uint32_t)(r * AST + c) * 2);
                ldsm_x4_t(vl4, sb + A_VL + (uint32_t)(r * AST + c) * 2);
                mma_bf16(acc_o[2 * nd + 0], pah[kc], vh4[0], vh4[1]);
                mma_bf16(acc_o[2 * nd + 1], pah[kc], vh4[2], vh4[3]);
                mma_bf16(acc_o[2 * nd + 0], pal[kc], vh4[0], vh4[1]);
                mma_bf16(acc_o[2 * nd + 1], pal[kc], vh4[2], vh4[3]);
                mma_bf16(acc_o[2 * nd + 0], pah[kc], vl4[0], vl4[1]);
                mma_bf16(acc_o[2 * nd + 1], pah[kc], vl4[2], vl4[3]);
            }
        }
    }

    // epilogue: un-transpose to ctx[b, l, h*64+d], emit bf16 hi/lo
    const float inv0 = 1.0f / l0;
    const float inv1 = 1.0f / l1;
    const int b = g / 12;
    const int h = g % 12;
    const int l_row = qt * 128 + w * 16 + gr;
    const size_t base0 = (size_t)b * 786432 + (size_t)l_row * 768 + h * 64;
    const size_t base1 = base0 + 8 * 768;
#pragma unroll
    for (int ni = 0; ni < 8; ni++) {
        const int d = ni * 8 + gc;
        uint32_t h0, lo0, h1, lo1;
        split_pair(acc_o[ni][0] * inv0, acc_o[ni][1] * inv0, h0, lo0);
        split_pair(acc_o[ni][2] * inv1, acc_o[ni][3] * inv1, h1, lo1);
        *(uint32_t*)(Ch + base0 + d) = h0;
        *(uint32_t*)(Cl + base0 + d) = lo0;
        *(uint32_t*)(Ch + base1 + d) = h1;
        *(uint32_t*)(Cl + base1 + d) = lo1;
    }
}

// ---------------------------------------------------------------------------
// Launch
// ---------------------------------------------------------------------------
extern "C" void kernel_launch(void* const* d_in, const int* in_sizes, int n_in,
                              void* d_out, int out_size)
{
    const float* x  = (const float*)d_in[0];
    const float* Wq = (const float*)d_in[1];
    const float* bq = (const float*)d_in[2];
    const float* Wk = (const float*)d_in[3];
    const float* bk = (const float*)d_in[4];
    const float* Wv = (const float*)d_in[5];
    const float* bv = (const float*)d_in[6];
    const float* Wo = (const float*)d_in[7];
    const float* bo = (const float*)d_in[8];
    float* out = (float*)d_out;

    __nv_bfloat16 *xh, *xl, *qh, *ql, *kh, *kl, *vh, *vl, *ch, *cl;
    __nv_bfloat16 *wqh, *wql, *wkh, *wkl, *wvh, *wvl, *woh, *wol;
    cudaGetSymbolAddress((void**)&xh,  g_xh);
    cudaGetSymbolAddress((void**)&xl,  g_xl);
    cudaGetSymbolAddress((void**)&qh,  g_qh);
    cudaGetSymbolAddress((void**)&ql,  g_ql);
    cudaGetSymbolAddress((void**)&kh,  g_kh);
    cudaGetSymbolAddress((void**)&kl,  g_kl);
    cudaGetSymbolAddress((void**)&vh,  g_vh);
    cudaGetSymbolAddress((void**)&vl,  g_vl);
    cudaGetSymbolAddress((void**)&ch,  g_ch);
    cudaGetSymbolAddress((void**)&cl,  g_cl);
    cudaGetSymbolAddress((void**)&wqh, g_wqh);
    cudaGetSymbolAddress((void**)&wql, g_wql);
    cudaGetSymbolAddress((void**)&wkh, g_wkh);
    cudaGetSymbolAddress((void**)&wkl, g_wkl);
    cudaGetSymbolAddress((void**)&wvh, g_wvh);
    cudaGetSymbolAddress((void**)&wvl, g_wvl);
    cudaGetSymbolAddress((void**)&woh, g_woh);
    cudaGetSymbolAddress((void**)&wol, g_wol);

    static bool attr_set = false;
    if (!attr_set) {
        cudaFuncSetAttribute(gemm_mma,
            cudaFuncAttributeMaxDynamicSharedMemorySize, GSM_TOTAL);
        cudaFuncSetAttribute(attn_tc,
            cudaFuncAttributeMaxDynamicSharedMemorySize, ASM_TOTAL);
        attr_set = true;
    }

    const int n_act = M_TOK * CDIM;
    split_f32<<<(n_act + 255) / 256, 256>>>(x, xh, xl, n_act);

    dim3 tb(32, 8), tg(CDIM / 32, CDIM / 32);
    transpose_split_w<<<tg, tb>>>(Wq, wqh, wql);
    transpose_split_w<<<tg, tb>>>(Wk, wkh, wkl);
    transpose_split_w<<<tg, tb>>>(Wv, wvh, wvl);
    transpose_split_w<<<tg, tb>>>(Wo, woh, wol);

    dim3 ggrid(M_TOK / 128, CDIM / 128);
    gemm_mma<<<ggrid, 256, GSM_TOTAL>>>(xh, xl, wqh, wql, bq, nullptr, qh, ql);
    gemm_mma<<<ggrid, 256, GSM_TOTAL>>>(xh, xl, wkh, wkl, bk, nullptr, kh, kl);
    gemm_mma<<<ggrid, 256, GSM_TOTAL>>>(xh, xl, wvh, wvl, bv, nullptr, vh, vl);

    attn_tc<<<dim3(8, 192), 256, ASM_TOTAL>>>(qh, ql, kh, kl, vh, vl, ch, cl);

    gemm_mma<<<ggrid, 256, GSM_TOTAL>>>(ch, cl, woh, wol, bo, out, nullptr, nullptr);
}